// round 5
// baseline (speedup 1.0000x reference)
#include <cuda_runtime.h>
#include <cuda_bf16.h>

#define NN 100000
#define EE 1600000
#define TILE 256

#define FMA_F32X2(d, a, b, c) \
    asm("fma.rn.f32x2 %0, %1, %2, %3;" : "=l"(d) : "l"(a), "l"(b), "l"(c))
#define PACK_DUP_F32X2(out, f) do { \
    unsigned _u = __float_as_uint(f); \
    asm("mov.b64 %0, {%1, %1};" : "=l"(out) : "r"(_u)); } while (0)
#define UNPACK_F32X2(lo, hi, in) \
    asm("mov.b64 {%0, %1}, %2;" : "=f"(lo), "=f"(hi) : "l"(in))

// ---- device scratch (no allocation) ----
__device__ float g_h1t[(size_t)64 * NN];        // h1 transposed [feat][node]
__device__ float g_At[3 * 64 * 64];             // composed head weights [h][l][i]
__device__ float g_bh[3 * 64];                  // composed head biases
__device__ float g_u1[64];                      // W2^T Ws^T wsc
__device__ float g_c1;
__device__ __nv_bfloat16 g_kh[(size_t)NN * 64];
__device__ __nv_bfloat16 g_qh[(size_t)NN * 64];
__device__ __nv_bfloat16 g_vh[(size_t)NN * 64];

// ---------------- prologue: compose weights (single kernel) ----------------
__global__ void prec1(const float* __restrict__ W2, const float* __restrict__ b2,
                      const float* __restrict__ Wk, const float* __restrict__ bk,
                      const float* __restrict__ Wq, const float* __restrict__ bq,
                      const float* __restrict__ Wv, const float* __restrict__ bv,
                      const float* __restrict__ Ws, const float* __restrict__ b_gate,
                      const float* __restrict__ Wsc, const float* __restrict__ bsc)
{
    int id = blockIdx.x * 256 + threadIdx.x;
    if (id < 12288) {
        int head = id >> 12, rem = id & 4095;
        int l = rem >> 6, i = rem & 63;
        const float* Wh = head == 0 ? Wk : head == 1 ? Wq : Wv;
        float s = 0.f;
        for (int j = 0; j < 64; j++) s = fmaf(Wh[i * 64 + j], W2[j * 64 + l], s);
        if (head == 2) s *= Wsc[i];
        g_At[head * 4096 + l * 64 + i] = s;
    } else if (id < 12352) {
        int i = id - 12288;
        float sk = bk[i], sq = bq[i], sv = bv[i];
        for (int j = 0; j < 64; j++) {
            sk = fmaf(Wk[i * 64 + j], b2[j], sk);
            sq = fmaf(Wq[i * 64 + j], b2[j], sq);
            sv = fmaf(Wv[i * 64 + j], b2[j], sv);
        }
        g_bh[i] = sk; g_bh[64 + i] = sq; g_bh[128 + i] = sv * Wsc[i];
        // u1[i] = sum_l (sum_j wsc_j Ws[j,l]) W2[l,i]
        float u1 = 0.f;
        for (int l = 0; l < 64; l++) {
            float ul = 0.f;
            for (int j = 0; j < 64; j++) ul = fmaf(Wsc[j], Ws[j * 64 + l], ul);
            u1 = fmaf(ul, W2[l * 64 + i], u1);
        }
        g_u1[i] = u1;
        if (i == 0) {
            float c = bsc[0];
            for (int j = 0; j < 64; j++) c = fmaf(Wsc[j], b_gate[j], c);
            for (int l = 0; l < 64; l++) {
                float ul = 0.f;
                for (int j = 0; j < 64; j++) ul = fmaf(Wsc[j], Ws[j * 64 + l], ul);
                c = fmaf(ul, b2[l], c);
            }
            g_c1 = c;
        }
    }
}

// ---------------- N1: h1 = relu(x @ W1^T + b1) — 4 nodes x 16 feats/thread ----
__global__ __launch_bounds__(TILE)
void n1_kernel(const float* __restrict__ x,
               const float* __restrict__ W1, const float* __restrict__ b1)
{
    extern __shared__ float sm[];
    float* w1t = sm;                 // 8192 : [i=128][j=64]
    float* bb  = w1t + 8192;         // 64
    float* xs  = bb + 64;            // 32 * 257

    const int tid = threadIdx.x;
    for (int idx = tid; idx < 8192; idx += TILE) {
        int j = idx >> 7, i = idx & 127;
        w1t[i * 64 + j] = W1[idx];
    }
    if (tid < 64) bb[tid] = b1[tid];
    __syncthreads();

    const int fh = tid >> 6;          // feature quarter: feats [fh*16, fh*16+16)
    const int np = tid & 63;          // node-in-group
    const int base = blockIdx.x * TILE;

    unsigned long long acc2[32];      // [node k][j2] : 4 nodes x 8 f32x2
    {
        const unsigned long long* bp = (const unsigned long long*)(bb + fh * 16);
        #pragma unroll
        for (int k = 0; k < 4; k++)
            #pragma unroll
            for (int j = 0; j < 8; j++) acc2[k * 8 + j] = bp[j];
    }

    for (int c = 0; c < 4; c++) {
        if (c) __syncthreads();
        for (int idx = tid; idx < 2048; idx += TILE) {
            int n = idx >> 3, i4 = idx & 7;
            int nn = base + n;
            float4 v = (nn < NN) ? ((const float4*)x)[(size_t)nn * 32 + c * 8 + i4]
                                 : make_float4(0.f, 0.f, 0.f, 0.f);
            xs[(i4 * 4 + 0) * 257 + n] = v.x;
            xs[(i4 * 4 + 1) * 257 + n] = v.y;
            xs[(i4 * 4 + 2) * 257 + n] = v.z;
            xs[(i4 * 4 + 3) * 257 + n] = v.w;
        }
        __syncthreads();
        #pragma unroll 2
        for (int i = 0; i < 32; i++) {
            const float* xr = xs + i * 257 + np;
            unsigned long long h0, h1, h2, h3;
            PACK_DUP_F32X2(h0, xr[0]);
            PACK_DUP_F32X2(h1, xr[64]);
            PACK_DUP_F32X2(h2, xr[128]);
            PACK_DUP_F32X2(h3, xr[192]);
            const ulonglong2* wr = (const ulonglong2*)(w1t + (c * 32 + i) * 64 + fh * 16);
            ulonglong2 wa = wr[0], wb = wr[1], wc = wr[2], wd = wr[3];
            unsigned long long w[8] = {wa.x, wa.y, wb.x, wb.y, wc.x, wc.y, wd.x, wd.y};
            #pragma unroll
            for (int j = 0; j < 8; j++) {
                FMA_F32X2(acc2[j],      h0, w[j], acc2[j]);
                FMA_F32X2(acc2[8 + j],  h1, w[j], acc2[8 + j]);
                FMA_F32X2(acc2[16 + j], h2, w[j], acc2[16 + j]);
                FMA_F32X2(acc2[24 + j], h3, w[j], acc2[24 + j]);
            }
        }
    }
    #pragma unroll
    for (int k = 0; k < 4; k++) {
        int node = base + np + 64 * k;
        if (node < NN) {
            #pragma unroll
            for (int j = 0; j < 8; j++) {
                float lo, hi;
                UNPACK_F32X2(lo, hi, acc2[k * 8 + j]);
                g_h1t[(size_t)(fh * 16 + 2 * j + 0) * NN + node] = fmaxf(lo, 0.f);
                g_h1t[(size_t)(fh * 16 + 2 * j + 1) * NN + node] = fmaxf(hi, 0.f);
            }
        }
    }
}

// ---------------- N2: score + heads — 4 nodes x 16 feats/thread ----------------
__device__ __forceinline__ unsigned pack_bf2(float a, float b) {
    __nv_bfloat162 h = __floats2bfloat162_rn(a, b);
    return *reinterpret_cast<unsigned*>(&h);
}

__global__ __launch_bounds__(TILE, 2)
void n2_kernel(float* __restrict__ out)
{
    extern __shared__ float sm[];
    float* at = sm;             // 12288
    float* bb = at + 12288;     // 256: bh(192) | u1(64)
    float* hs = bb + 256;       // 64 * 256

    const int tid = threadIdx.x;
    const int base = blockIdx.x * TILE;

    for (int idx = tid; idx < 3072; idx += TILE)
        ((float4*)at)[idx] = ((const float4*)g_At)[idx];
    if (tid < 192) bb[tid] = g_bh[tid];
    if (tid < 64)  bb[192 + tid] = g_u1[tid];

    for (int idx = tid; idx < 4096; idx += TILE) {
        int f = idx >> 6, n4 = idx & 63;
        int n = n4 * 4;
        float4 v = (base + n + 3 < NN)
                 ? *(const float4*)(g_h1t + (size_t)f * NN + base + n)
                 : make_float4(0.f, 0.f, 0.f, 0.f);
        *(float4*)(hs + f * 256 + n) = v;
    }
    __syncthreads();

    const int fh = tid >> 6;
    const int np = tid & 63;

    // score on fh==0 warps (warp-uniform branch)
    if (fh == 0) {
        float s0 = g_c1, s1 = g_c1, s2 = g_c1, s3 = g_c1;
        #pragma unroll 4
        for (int l = 0; l < 64; l++) {
            float ul = bb[192 + l];
            const float* hr = hs + l * 256 + np;
            s0 = fmaf(hr[0],   ul, s0);
            s1 = fmaf(hr[64],  ul, s1);
            s2 = fmaf(hr[128], ul, s2);
            s3 = fmaf(hr[192], ul, s3);
        }
        if (base + np       < NN) out[base + np]       = s0;
        if (base + np + 64  < NN) out[base + np + 64]  = s1;
        if (base + np + 128 < NN) out[base + np + 128] = s2;
        if (base + np + 192 < NN) out[base + np + 192] = s3;
    }

    #pragma unroll 1
    for (int h = 0; h < 3; h++) {
        unsigned long long acc2[32];
        {
            const unsigned long long* bp = (const unsigned long long*)(bb + h * 64 + fh * 16);
            #pragma unroll
            for (int k = 0; k < 4; k++)
                #pragma unroll
                for (int j = 0; j < 8; j++) acc2[k * 8 + j] = bp[j];
        }
        const float* ah = at + h * 4096 + fh * 16;
        #pragma unroll 2
        for (int l = 0; l < 64; l++) {
            const float* hr = hs + l * 256 + np;
            unsigned long long h0, h1, h2, h3;
            PACK_DUP_F32X2(h0, hr[0]);
            PACK_DUP_F32X2(h1, hr[64]);
            PACK_DUP_F32X2(h2, hr[128]);
            PACK_DUP_F32X2(h3, hr[192]);
            const ulonglong2* wr = (const ulonglong2*)(ah + l * 64);
            ulonglong2 wa = wr[0], wb = wr[1], wc = wr[2], wd = wr[3];
            unsigned long long w[8] = {wa.x, wa.y, wb.x, wb.y, wc.x, wc.y, wd.x, wd.y};
            #pragma unroll
            for (int j = 0; j < 8; j++) {
                FMA_F32X2(acc2[j],      h0, w[j], acc2[j]);
                FMA_F32X2(acc2[8 + j],  h1, w[j], acc2[8 + j]);
                FMA_F32X2(acc2[16 + j], h2, w[j], acc2[16 + j]);
                FMA_F32X2(acc2[24 + j], h3, w[j], acc2[24 + j]);
            }
        }
        __nv_bfloat16* dp = (h == 0) ? g_kh : (h == 1) ? g_qh : g_vh;
        #pragma unroll
        for (int k = 0; k < 4; k++) {
            int node = base + np + 64 * k;
            if (node < NN) {
                uint4 u;
                float a0, a1, b0, b1, c0, c1, d0, d1;
                UNPACK_F32X2(a0, a1, acc2[k * 8 + 0]);
                UNPACK_F32X2(b0, b1, acc2[k * 8 + 1]);
                UNPACK_F32X2(c0, c1, acc2[k * 8 + 2]);
                UNPACK_F32X2(d0, d1, acc2[k * 8 + 3]);
                u.x = pack_bf2(a0, a1); u.y = pack_bf2(b0, b1);
                u.z = pack_bf2(c0, c1); u.w = pack_bf2(d0, d1);
                *(uint4*)(dp + (size_t)node * 64 + fh * 16) = u;
                UNPACK_F32X2(a0, a1, acc2[k * 8 + 4]);
                UNPACK_F32X2(b0, b1, acc2[k * 8 + 5]);
                UNPACK_F32X2(c0, c1, acc2[k * 8 + 6]);
                UNPACK_F32X2(d0, d1, acc2[k * 8 + 7]);
                u.x = pack_bf2(a0, a1); u.y = pack_bf2(b0, b1);
                u.z = pack_bf2(c0, c1); u.w = pack_bf2(d0, d1);
                *(uint4*)(dp + (size_t)node * 64 + fh * 16 + 8) = u;
            }
        }
    }
}

// ---------------- edge kernel: 4 lanes/edge, bf16 ----------------
__device__ __forceinline__ float sigf(float x) {
    float t;
    asm("tanh.approx.f32 %0, %1;" : "=f"(t) : "f"(x * 0.5f));
    return fmaf(t, 0.5f, 0.5f);
}
__device__ __forceinline__ float2 bf2f(unsigned u) {
    __nv_bfloat162 h = *reinterpret_cast<__nv_bfloat162*>(&u);
    return __bfloat1622float2(h);
}
__device__ __forceinline__ float edge8(uint4 kk, uint4 qq, uint4 vv) {
    float s = 0.f;
    {
        float2 kf = bf2f(kk.x), qf = bf2f(qq.x), vf = bf2f(vv.x);
        s += sigf(kf.x + qf.x) * vf.x + sigf(kf.y + qf.y) * vf.y;
    }
    {
        float2 kf = bf2f(kk.y), qf = bf2f(qq.y), vf = bf2f(vv.y);
        s += sigf(kf.x + qf.x) * vf.x + sigf(kf.y + qf.y) * vf.y;
    }
    {
        float2 kf = bf2f(kk.z), qf = bf2f(qq.z), vf = bf2f(vv.z);
        s += sigf(kf.x + qf.x) * vf.x + sigf(kf.y + qf.y) * vf.y;
    }
    {
        float2 kf = bf2f(kk.w), qf = bf2f(qq.w), vf = bf2f(vv.w);
        s += sigf(kf.x + qf.x) * vf.x + sigf(kf.y + qf.y) * vf.y;
    }
    return s;
}

__global__ __launch_bounds__(256)
void edge_kernel(const int* __restrict__ ei, float* __restrict__ out)
{
    int t = blockIdx.x * 256 + threadIdx.x;
    int e = t >> 2;
    if (e >= EE) return;
    int sub = t & 3;

    int src = ei[e];
    int dst = ei[EE + e];

    const uint4* kp = (const uint4*)(g_kh + (size_t)dst * 64 + sub * 16);
    const uint4* qp = (const uint4*)(g_qh + (size_t)src * 64 + sub * 16);
    const uint4* vp = (const uint4*)(g_vh + (size_t)src * 64 + sub * 16);
    uint4 k0 = kp[0], k1 = kp[1];
    uint4 q0 = qp[0], q1 = qp[1];
    uint4 v0 = vp[0], v1 = vp[1];

    float s = edge8(k0, q0, v0) + edge8(k1, q1, v1);

    s += __shfl_down_sync(0xffffffffu, s, 2, 4);
    s += __shfl_down_sync(0xffffffffu, s, 1, 4);
    if (sub == 0) atomicAdd(out + dst, s);
}

extern "C" void kernel_launch(void* const* d_in, const int* in_sizes, int n_in,
                              void* d_out, int out_size)
{
    const float* x      = (const float*)d_in[0];
    const int*   ei     = (const int*)d_in[1];
    const float* W1     = (const float*)d_in[2];
    const float* b1     = (const float*)d_in[3];
    const float* W2     = (const float*)d_in[4];
    const float* b2     = (const float*)d_in[5];
    const float* Wk     = (const float*)d_in[6];
    const float* bk     = (const float*)d_in[7];
    const float* Wq     = (const float*)d_in[8];
    const float* bq     = (const float*)d_in[9];
    const float* Wv     = (const float*)d_in[10];
    const float* bv     = (const float*)d_in[11];
    const float* Ws     = (const float*)d_in[12];
    const float* b_gate = (const float*)d_in[13];
    const float* Wsc    = (const float*)d_in[14];
    const float* bsc    = (const float*)d_in[15];
    float* out = (float*)d_out;

    size_t smem1 = (8192 + 64 + 32 * 257) * sizeof(float);
    size_t smem2 = (12288 + 256 + 64 * 256) * sizeof(float);
    cudaFuncSetAttribute(n1_kernel, cudaFuncAttributeMaxDynamicSharedMemorySize, (int)smem1);
    cudaFuncSetAttribute(n2_kernel, cudaFuncAttributeMaxDynamicSharedMemorySize, (int)smem2);

    prec1<<<49, 256>>>(W2, b2, Wk, bk, Wq, bq, Wv, bv, Ws, b_gate, Wsc, bsc);

    int nblocks = (NN + TILE - 1) / TILE;
    n1_kernel<<<nblocks, TILE, smem1>>>(x, W1, b1);
    n2_kernel<<<nblocks, TILE, smem2>>>(out);

    edge_kernel<<<(EE * 4) / 256, 256>>>(ei, out);
}

// round 6
// speedup vs baseline: 1.0776x; 1.0776x over previous
#include <cuda_runtime.h>
#include <cuda_bf16.h>

#define NN 100000
#define EE 1600000
#define TILE 256

#define FMA_F32X2(d, a, b, c) \
    asm("fma.rn.f32x2 %0, %1, %2, %3;" : "=l"(d) : "l"(a), "l"(b), "l"(c))
#define PACK_DUP_F32X2(out, f) do { \
    unsigned _u = __float_as_uint(f); \
    asm("mov.b64 %0, {%1, %1};" : "=l"(out) : "r"(_u)); } while (0)
#define UNPACK_F32X2(lo, hi, in) \
    asm("mov.b64 {%0, %1}, %2;" : "=f"(lo), "=f"(hi) : "l"(in))

// ---- device scratch (no allocation) ----
__device__ float g_h1t[(size_t)64 * NN];        // h1 transposed [feat][node]
__device__ float g_At[3 * 64 * 64];             // composed head weights [h][l][i]
__device__ float g_bh[3 * 64];                  // composed head biases
__device__ float g_u1[64];                      // W2^T Ws^T wsc
__device__ float g_c1;
__device__ __nv_bfloat16 g_kh[(size_t)NN * 64];
__device__ __nv_bfloat16 g_qh[(size_t)NN * 64];
__device__ __nv_bfloat16 g_vh[(size_t)NN * 64];

// ---------------- prologue: compose weights ----------------
__global__ void prec1(const float* __restrict__ W2, const float* __restrict__ b2,
                      const float* __restrict__ Wk, const float* __restrict__ bk,
                      const float* __restrict__ Wq, const float* __restrict__ bq,
                      const float* __restrict__ Wv, const float* __restrict__ bv,
                      const float* __restrict__ Ws, const float* __restrict__ b_gate,
                      const float* __restrict__ Wsc, const float* __restrict__ bsc)
{
    int id = blockIdx.x * 256 + threadIdx.x;
    if (id < 12288) {
        int head = id >> 12, rem = id & 4095;
        int l = rem >> 6, i = rem & 63;
        const float* Wh = head == 0 ? Wk : head == 1 ? Wq : Wv;
        float s = 0.f;
        for (int j = 0; j < 64; j++) s = fmaf(Wh[i * 64 + j], W2[j * 64 + l], s);
        if (head == 2) s *= Wsc[i];
        g_At[head * 4096 + l * 64 + i] = s;
    } else if (id < 12352) {
        int i = id - 12288;
        float sk = bk[i], sq = bq[i], sv = bv[i];
        for (int j = 0; j < 64; j++) {
            sk = fmaf(Wk[i * 64 + j], b2[j], sk);
            sq = fmaf(Wq[i * 64 + j], b2[j], sq);
            sv = fmaf(Wv[i * 64 + j], b2[j], sv);
        }
        g_bh[i] = sk; g_bh[64 + i] = sq; g_bh[128 + i] = sv * Wsc[i];
        float u1 = 0.f;
        for (int l = 0; l < 64; l++) {
            float ul = 0.f;
            for (int j = 0; j < 64; j++) ul = fmaf(Wsc[j], Ws[j * 64 + l], ul);
            u1 = fmaf(ul, W2[l * 64 + i], u1);
        }
        g_u1[i] = u1;
        if (i == 0) {
            float c = bsc[0];
            for (int j = 0; j < 64; j++) c = fmaf(Wsc[j], b_gate[j], c);
            for (int l = 0; l < 64; l++) {
                float ul = 0.f;
                for (int j = 0; j < 64; j++) ul = fmaf(Wsc[j], Ws[j * 64 + l], ul);
                c = fmaf(ul, b2[l], c);
            }
            g_c1 = c;
        }
    }
}

// 8 FMAs on one weight pair across 4 nodes (keeps 1 ulonglong2 live)
#define STEP_W2(acc, J, wpair, h0, h1, h2, h3) do { \
    FMA_F32X2(acc[(J)],      h0, (wpair).x, acc[(J)]); \
    FMA_F32X2(acc[(J)+1],    h0, (wpair).y, acc[(J)+1]); \
    FMA_F32X2(acc[8+(J)],    h1, (wpair).x, acc[8+(J)]); \
    FMA_F32X2(acc[8+(J)+1],  h1, (wpair).y, acc[8+(J)+1]); \
    FMA_F32X2(acc[16+(J)],   h2, (wpair).x, acc[16+(J)]); \
    FMA_F32X2(acc[16+(J)+1], h2, (wpair).y, acc[16+(J)+1]); \
    FMA_F32X2(acc[24+(J)],   h3, (wpair).x, acc[24+(J)]); \
    FMA_F32X2(acc[24+(J)+1], h3, (wpair).y, acc[24+(J)+1]); } while (0)

// ---------------- N1: h1 = relu(x @ W1^T + b1) — 4 nodes x 16 feats/thread ----
__global__ __launch_bounds__(TILE, 2)
void n1_kernel(const float* __restrict__ x,
               const float* __restrict__ W1, const float* __restrict__ b1)
{
    extern __shared__ float sm[];
    float* w1t = sm;                 // 8192 : [i=128][j=64]
    float* bb  = w1t + 8192;         // 64
    float* xs  = bb + 64;            // 32 * 257

    const int tid = threadIdx.x;
    for (int idx = tid; idx < 8192; idx += TILE) {
        int j = idx >> 7, i = idx & 127;
        w1t[i * 64 + j] = W1[idx];
    }
    if (tid < 64) bb[tid] = b1[tid];
    __syncthreads();

    const int fh = tid >> 6;          // feature quarter
    const int np = tid & 63;          // node-in-group
    const int base = blockIdx.x * TILE;

    unsigned long long acc2[32];
    {
        const unsigned long long* bp = (const unsigned long long*)(bb + fh * 16);
        #pragma unroll
        for (int k = 0; k < 4; k++)
            #pragma unroll
            for (int j = 0; j < 8; j++) acc2[k * 8 + j] = bp[j];
    }

    for (int c = 0; c < 4; c++) {
        if (c) __syncthreads();
        for (int idx = tid; idx < 2048; idx += TILE) {
            int n = idx >> 3, i4 = idx & 7;
            int nn = base + n;
            float4 v = (nn < NN) ? ((const float4*)x)[(size_t)nn * 32 + c * 8 + i4]
                                 : make_float4(0.f, 0.f, 0.f, 0.f);
            xs[(i4 * 4 + 0) * 257 + n] = v.x;
            xs[(i4 * 4 + 1) * 257 + n] = v.y;
            xs[(i4 * 4 + 2) * 257 + n] = v.z;
            xs[(i4 * 4 + 3) * 257 + n] = v.w;
        }
        __syncthreads();
        const float* wbase = w1t + c * 32 * 64 + fh * 16;
        for (int i = 0; i < 32; i++) {
            const float* xr = xs + i * 257 + np;
            unsigned long long h0, h1, h2, h3;
            PACK_DUP_F32X2(h0, xr[0]);
            PACK_DUP_F32X2(h1, xr[64]);
            PACK_DUP_F32X2(h2, xr[128]);
            PACK_DUP_F32X2(h3, xr[192]);
            const ulonglong2* wr = (const ulonglong2*)(wbase + i * 64);
            { ulonglong2 w = wr[0]; STEP_W2(acc2, 0, w, h0, h1, h2, h3); }
            { ulonglong2 w = wr[1]; STEP_W2(acc2, 2, w, h0, h1, h2, h3); }
            { ulonglong2 w = wr[2]; STEP_W2(acc2, 4, w, h0, h1, h2, h3); }
            { ulonglong2 w = wr[3]; STEP_W2(acc2, 6, w, h0, h1, h2, h3); }
        }
    }
    #pragma unroll
    for (int k = 0; k < 4; k++) {
        int node = base + np + 64 * k;
        if (node < NN) {
            #pragma unroll
            for (int j = 0; j < 8; j++) {
                float lo, hi;
                UNPACK_F32X2(lo, hi, acc2[k * 8 + j]);
                g_h1t[(size_t)(fh * 16 + 2 * j + 0) * NN + node] = fmaxf(lo, 0.f);
                g_h1t[(size_t)(fh * 16 + 2 * j + 1) * NN + node] = fmaxf(hi, 0.f);
            }
        }
    }
}

// ---------------- N2: score + heads — 4 nodes x 16 feats/thread ----------------
__device__ __forceinline__ unsigned pack_bf2(float a, float b) {
    __nv_bfloat162 h = __floats2bfloat162_rn(a, b);
    return *reinterpret_cast<unsigned*>(&h);
}

__global__ __launch_bounds__(TILE, 2)
void n2_kernel(float* __restrict__ out)
{
    extern __shared__ float sm[];
    float* at = sm;             // 12288
    float* bb = at + 12288;     // 256: bh(192) | u1(64)
    float* hs = bb + 256;       // 64 * 256

    const int tid = threadIdx.x;
    const int base = blockIdx.x * TILE;

    for (int idx = tid; idx < 3072; idx += TILE)
        ((float4*)at)[idx] = ((const float4*)g_At)[idx];
    if (tid < 192) bb[tid] = g_bh[tid];
    if (tid < 64)  bb[192 + tid] = g_u1[tid];

    for (int idx = tid; idx < 4096; idx += TILE) {
        int f = idx >> 6, n4 = idx & 63;
        int n = n4 * 4;
        float4 v = (base + n + 3 < NN)
                 ? *(const float4*)(g_h1t + (size_t)f * NN + base + n)
                 : make_float4(0.f, 0.f, 0.f, 0.f);
        *(float4*)(hs + f * 256 + n) = v;
    }
    __syncthreads();

    const int fh = tid >> 6;
    const int np = tid & 63;

    if (fh == 0) {  // warp-uniform: warps 0-1 compute scores
        float s0 = g_c1, s1 = g_c1, s2 = g_c1, s3 = g_c1;
        #pragma unroll 4
        for (int l = 0; l < 64; l++) {
            float ul = bb[192 + l];
            const float* hr = hs + l * 256 + np;
            s0 = fmaf(hr[0],   ul, s0);
            s1 = fmaf(hr[64],  ul, s1);
            s2 = fmaf(hr[128], ul, s2);
            s3 = fmaf(hr[192], ul, s3);
        }
        if (base + np       < NN) out[base + np]       = s0;
        if (base + np + 64  < NN) out[base + np + 64]  = s1;
        if (base + np + 128 < NN) out[base + np + 128] = s2;
        if (base + np + 192 < NN) out[base + np + 192] = s3;
    }

    #pragma unroll 1
    for (int h = 0; h < 3; h++) {
        unsigned long long acc2[32];
        {
            const unsigned long long* bp = (const unsigned long long*)(bb + h * 64 + fh * 16);
            #pragma unroll
            for (int k = 0; k < 4; k++)
                #pragma unroll
                for (int j = 0; j < 8; j++) acc2[k * 8 + j] = bp[j];
        }
        const float* ah = at + h * 4096 + fh * 16;
        for (int l = 0; l < 64; l++) {
            const float* hr = hs + l * 256 + np;
            unsigned long long h0, h1, h2, h3;
            PACK_DUP_F32X2(h0, hr[0]);
            PACK_DUP_F32X2(h1, hr[64]);
            PACK_DUP_F32X2(h2, hr[128]);
            PACK_DUP_F32X2(h3, hr[192]);
            const ulonglong2* wr = (const ulonglong2*)(ah + l * 64);
            { ulonglong2 w = wr[0]; STEP_W2(acc2, 0, w, h0, h1, h2, h3); }
            { ulonglong2 w = wr[1]; STEP_W2(acc2, 2, w, h0, h1, h2, h3); }
            { ulonglong2 w = wr[2]; STEP_W2(acc2, 4, w, h0, h1, h2, h3); }
            { ulonglong2 w = wr[3]; STEP_W2(acc2, 6, w, h0, h1, h2, h3); }
        }
        __nv_bfloat16* dp = (h == 0) ? g_kh : (h == 1) ? g_qh : g_vh;
        #pragma unroll
        for (int k = 0; k < 4; k++) {
            int node = base + np + 64 * k;
            if (node < NN) {
                uint4 u;
                float a0, a1, b0, b1, c0, c1, d0, d1;
                UNPACK_F32X2(a0, a1, acc2[k * 8 + 0]);
                UNPACK_F32X2(b0, b1, acc2[k * 8 + 1]);
                UNPACK_F32X2(c0, c1, acc2[k * 8 + 2]);
                UNPACK_F32X2(d0, d1, acc2[k * 8 + 3]);
                u.x = pack_bf2(a0, a1); u.y = pack_bf2(b0, b1);
                u.z = pack_bf2(c0, c1); u.w = pack_bf2(d0, d1);
                *(uint4*)(dp + (size_t)node * 64 + fh * 16) = u;
                UNPACK_F32X2(a0, a1, acc2[k * 8 + 4]);
                UNPACK_F32X2(b0, b1, acc2[k * 8 + 5]);
                UNPACK_F32X2(c0, c1, acc2[k * 8 + 6]);
                UNPACK_F32X2(d0, d1, acc2[k * 8 + 7]);
                u.x = pack_bf2(a0, a1); u.y = pack_bf2(b0, b1);
                u.z = pack_bf2(c0, c1); u.w = pack_bf2(d0, d1);
                *(uint4*)(dp + (size_t)node * 64 + fh * 16 + 8) = u;
            }
        }
    }
}

// ---------------- edge kernel: 4 lanes/edge, bf16 (unchanged, 51us) ----------------
__device__ __forceinline__ float sigf(float x) {
    float t;
    asm("tanh.approx.f32 %0, %1;" : "=f"(t) : "f"(x * 0.5f));
    return fmaf(t, 0.5f, 0.5f);
}
__device__ __forceinline__ float2 bf2f(unsigned u) {
    __nv_bfloat162 h = *reinterpret_cast<__nv_bfloat162*>(&u);
    return __bfloat1622float2(h);
}
__device__ __forceinline__ float edge8(uint4 kk, uint4 qq, uint4 vv) {
    float s = 0.f;
    {
        float2 kf = bf2f(kk.x), qf = bf2f(qq.x), vf = bf2f(vv.x);
        s += sigf(kf.x + qf.x) * vf.x + sigf(kf.y + qf.y) * vf.y;
    }
    {
        float2 kf = bf2f(kk.y), qf = bf2f(qq.y), vf = bf2f(vv.y);
        s += sigf(kf.x + qf.x) * vf.x + sigf(kf.y + qf.y) * vf.y;
    }
    {
        float2 kf = bf2f(kk.z), qf = bf2f(qq.z), vf = bf2f(vv.z);
        s += sigf(kf.x + qf.x) * vf.x + sigf(kf.y + qf.y) * vf.y;
    }
    {
        float2 kf = bf2f(kk.w), qf = bf2f(qq.w), vf = bf2f(vv.w);
        s += sigf(kf.x + qf.x) * vf.x + sigf(kf.y + qf.y) * vf.y;
    }
    return s;
}

__global__ __launch_bounds__(256)
void edge_kernel(const int* __restrict__ ei, float* __restrict__ out)
{
    int t = blockIdx.x * 256 + threadIdx.x;
    int e = t >> 2;
    if (e >= EE) return;
    int sub = t & 3;

    int src = ei[e];
    int dst = ei[EE + e];

    const uint4* kp = (const uint4*)(g_kh + (size_t)dst * 64 + sub * 16);
    const uint4* qp = (const uint4*)(g_qh + (size_t)src * 64 + sub * 16);
    const uint4* vp = (const uint4*)(g_vh + (size_t)src * 64 + sub * 16);
    uint4 k0 = kp[0], k1 = kp[1];
    uint4 q0 = qp[0], q1 = qp[1];
    uint4 v0 = vp[0], v1 = vp[1];

    float s = edge8(k0, q0, v0) + edge8(k1, q1, v1);

    s += __shfl_down_sync(0xffffffffu, s, 2, 4);
    s += __shfl_down_sync(0xffffffffu, s, 1, 4);
    if (sub == 0) atomicAdd(out + dst, s);
}

extern "C" void kernel_launch(void* const* d_in, const int* in_sizes, int n_in,
                              void* d_out, int out_size)
{
    const float* x      = (const float*)d_in[0];
    const int*   ei     = (const int*)d_in[1];
    const float* W1     = (const float*)d_in[2];
    const float* b1     = (const float*)d_in[3];
    const float* W2     = (const float*)d_in[4];
    const float* b2     = (const float*)d_in[5];
    const float* Wk     = (const float*)d_in[6];
    const float* bk     = (const float*)d_in[7];
    const float* Wq     = (const float*)d_in[8];
    const float* bq     = (const float*)d_in[9];
    const float* Wv     = (const float*)d_in[10];
    const float* bv     = (const float*)d_in[11];
    const float* Ws     = (const float*)d_in[12];
    const float* b_gate = (const float*)d_in[13];
    const float* Wsc    = (const float*)d_in[14];
    const float* bsc    = (const float*)d_in[15];
    float* out = (float*)d_out;

    size_t smem1 = (8192 + 64 + 32 * 257) * sizeof(float);
    size_t smem2 = (12288 + 256 + 64 * 256) * sizeof(float);
    cudaFuncSetAttribute(n1_kernel, cudaFuncAttributeMaxDynamicSharedMemorySize, (int)smem1);
    cudaFuncSetAttribute(n2_kernel, cudaFuncAttributeMaxDynamicSharedMemorySize, (int)smem2);

    prec1<<<49, 256>>>(W2, b2, Wk, bk, Wq, bq, Wv, bv, Ws, b_gate, Wsc, bsc);

    int nblocks = (NN + TILE - 1) / TILE;
    n1_kernel<<<nblocks, TILE, smem1>>>(x, W1, b1);
    n2_kernel<<<nblocks, TILE, smem2>>>(out);

    edge_kernel<<<(EE * 4) / 256, 256>>>(ei, out);
}